// round 1
// baseline (speedup 1.0000x reference)
#include <cuda_runtime.h>
#include <cstdint>
#include <cstdio>

// Problem constants (fixed by the dataset)
#define NODE_DIM 128
#define CTX_DIM  256
#define OUT_DIM  256
#define IN_DIM   384          // 3 * NODE_DIM
#define N_COEF   7            // GRID_SIZE + SPLINE_ORDER
#define K_TOTAL  3072         // IN_DIM + IN_DIM * N_COEF
#define MAX_EDGES 100000

// -------- device scratch (static; no runtime allocation allowed) ----------
__device__ float g_xc[(size_t)MAX_EDGES * NODE_DIM];          // ctx projection (51 MB)
__device__ float g_act[(size_t)MAX_EDGES * K_TOTAL];          // activations (1.23 GB)
__device__ float g_weff[(size_t)OUT_DIM * K_TOTAL];           // fused weights (3 MB)

// ---------------------------------------------------------------------------
// Kernel 0: W_eff[o][k] = base_weight for k<384, else spline_weight*scaler
// ---------------------------------------------------------------------------
__global__ void prep_weff(const float* __restrict__ bw,
                          const float* __restrict__ sw,
                          const float* __restrict__ ss,
                          float* __restrict__ W)
{
    int t = blockIdx.x * blockDim.x + threadIdx.x;
    if (t >= OUT_DIM * K_TOTAL) return;
    int o = t / K_TOTAL;
    int k = t - o * K_TOTAL;
    float v;
    if (k < IN_DIM) {
        v = bw[o * IN_DIM + k];
    } else {
        int r = k - IN_DIM;
        int i = r / N_COEF;
        int c = r - i * N_COEF;
        v = sw[((size_t)o * IN_DIM + i) * N_COEF + c] * ss[o * IN_DIM + i];
    }
    W[t] = v;
}

// ---------------------------------------------------------------------------
// Generic NT GEMM: C[m][n] = sum_k A[m][k]*B[n][k] (+ bias[n])
// BM=BN=128, BK=16, 256 threads, 8x8 microtile, double-buffered smem.
// ---------------------------------------------------------------------------
__global__ __launch_bounds__(256, 2)
void gemm_nt(const float* __restrict__ A, const float* __restrict__ B,
             const float* __restrict__ bias, float* __restrict__ C,
             int M, int N, int K)
{
    constexpr int BM = 128, BN = 128, BK = 16;
    __shared__ float As[2][BK][BM];
    __shared__ float Bs[2][BK][BN];

    const int tid = threadIdx.x;
    const int tx  = tid & 15;      // n direction (16)
    const int ty  = tid >> 4;      // m direction (16)
    const int m0  = blockIdx.y * BM;
    const int n0  = blockIdx.x * BN;
    const int lr  = tid >> 2;        // 0..63
    const int lc  = (tid & 3) * 4;   // 0,4,8,12

    float acc[8][8];
#pragma unroll
    for (int i = 0; i < 8; ++i)
#pragma unroll
        for (int j = 0; j < 8; ++j) acc[i][j] = 0.f;

    auto loadTile = [&](int k0, int buf) {
#pragma unroll
        for (int h = 0; h < 2; ++h) {
            int m = m0 + h * 64 + lr;
            float4 v = make_float4(0.f, 0.f, 0.f, 0.f);
            if (m < M) v = *reinterpret_cast<const float4*>(&A[(size_t)m * K + k0 + lc]);
            As[buf][lc + 0][h * 64 + lr] = v.x;
            As[buf][lc + 1][h * 64 + lr] = v.y;
            As[buf][lc + 2][h * 64 + lr] = v.z;
            As[buf][lc + 3][h * 64 + lr] = v.w;
        }
#pragma unroll
        for (int h = 0; h < 2; ++h) {
            int n = n0 + h * 64 + lr;
            float4 v = make_float4(0.f, 0.f, 0.f, 0.f);
            if (n < N) v = *reinterpret_cast<const float4*>(&B[(size_t)n * K + k0 + lc]);
            Bs[buf][lc + 0][h * 64 + lr] = v.x;
            Bs[buf][lc + 1][h * 64 + lr] = v.y;
            Bs[buf][lc + 2][h * 64 + lr] = v.z;
            Bs[buf][lc + 3][h * 64 + lr] = v.w;
        }
    };

    loadTile(0, 0);
    __syncthreads();

    const int nk = K / BK;
    for (int t = 0; t < nk; ++t) {
        const int buf = t & 1;
        if (t + 1 < nk) loadTile((t + 1) * BK, buf ^ 1);

#pragma unroll
        for (int k = 0; k < BK; ++k) {
            float4 a0 = *reinterpret_cast<const float4*>(&As[buf][k][ty * 4]);
            float4 a1 = *reinterpret_cast<const float4*>(&As[buf][k][64 + ty * 4]);
            float4 b0 = *reinterpret_cast<const float4*>(&Bs[buf][k][tx * 4]);
            float4 b1 = *reinterpret_cast<const float4*>(&Bs[buf][k][64 + tx * 4]);
            float a[8] = {a0.x, a0.y, a0.z, a0.w, a1.x, a1.y, a1.z, a1.w};
            float b[8] = {b0.x, b0.y, b0.z, b0.w, b1.x, b1.y, b1.z, b1.w};
#pragma unroll
            for (int i = 0; i < 8; ++i)
#pragma unroll
                for (int j = 0; j < 8; ++j)
                    acc[i][j] += a[i] * b[j];
        }
        __syncthreads();
    }

    // epilogue
#pragma unroll
    for (int i = 0; i < 8; ++i) {
        int m = m0 + ((i < 4) ? (ty * 4 + i) : (64 + ty * 4 + i - 4));
        if (m >= M) continue;
#pragma unroll
        for (int jh = 0; jh < 2; ++jh) {
            int n = n0 + jh * 64 + tx * 4;
            if (n + 3 >= N && n >= N) continue;
            float4 v;
            float b0 = bias ? bias[n + 0] : 0.f;
            float b1 = bias ? bias[n + 1] : 0.f;
            float b2 = bias ? bias[n + 2] : 0.f;
            float b3 = bias ? bias[n + 3] : 0.f;
            v.x = acc[i][jh * 4 + 0] + b0;
            v.y = acc[i][jh * 4 + 1] + b1;
            v.z = acc[i][jh * 4 + 2] + b2;
            v.w = acc[i][jh * 4 + 3] + b3;
            *reinterpret_cast<float4*>(&C[(size_t)m * N + n]) = v;
        }
    }
}

// ---------------------------------------------------------------------------
// Kernel 2: build activation matrix.
//   act[n][i]            = silu(x_i)              (i in 0..383)
//   act[n][384 + 7*i+c]  = bspline_c(x_i)         (c in 0..6)
// x_i: i<128 -> node[p0][i], i<256 -> node[p1][i-128], else -> xc[n][i-256]
// B-spline denominators depend only on the grid -> precomputed reciprocals.
// ---------------------------------------------------------------------------
__global__ void build_act(const float* __restrict__ node,
                          const float* __restrict__ xc,
                          const int*   __restrict__ pairs,
                          const float* __restrict__ grid,
                          float* __restrict__ act,
                          int nEdges)
{
    __shared__ float g[11];
    __shared__ float inv[3][11];
    if (threadIdx.x < 11) g[threadIdx.x] = grid[threadIdx.x];  // all rows identical
    __syncthreads();
    if (threadIdx.x < 11) {
        int j = threadIdx.x;
#pragma unroll
        for (int k = 1; k <= 3; ++k)
            if (j <= 10 - k) inv[k - 1][j] = 1.f / (g[j + k] - g[j]);
    }
    __syncthreads();

    int t = blockIdx.x * blockDim.x + threadIdx.x;
    int total = nEdges * IN_DIM;
    if (t >= total) return;

    int n = t / IN_DIM;
    int i = t - n * IN_DIM;

    float x;
    if (i < NODE_DIM) {
        int p = pairs[2 * n];
        x = node[(size_t)p * NODE_DIM + i];
    } else if (i < 2 * NODE_DIM) {
        int p = pairs[2 * n + 1];
        x = node[(size_t)p * NODE_DIM + (i - NODE_DIM)];
    } else {
        x = xc[(size_t)n * NODE_DIM + (i - 2 * NODE_DIM)];
    }

    // silu
    float s = x / (1.f + expf(-x));

    // Cox-de Boor, order 3, grid of 11 points -> 7 final bases
    float b[10];
#pragma unroll
    for (int j = 0; j < 10; ++j)
        b[j] = (x >= g[j] && x < g[j + 1]) ? 1.f : 0.f;
#pragma unroll
    for (int k = 1; k <= 3; ++k) {
#pragma unroll
        for (int j = 0; j < 10; ++j) {
            if (j < 10 - k) {
                b[j] = (x - g[j]) * inv[k - 1][j] * b[j]
                     + (g[j + k + 1] - x) * inv[k - 1][j + 1] * b[j + 1];
            }
        }
    }

    size_t base = (size_t)n * K_TOTAL;
    act[base + i] = s;
#pragma unroll
    for (int c = 0; c < N_COEF; ++c)
        act[base + IN_DIM + (size_t)i * N_COEF + c] = b[c];
}

// ---------------------------------------------------------------------------
extern "C" void kernel_launch(void* const* d_in, const int* in_sizes, int n_in,
                              void* d_out, int out_size)
{
    const float* node  = (const float*)d_in[0];   // (100000,128)
    const float* cemb  = (const float*)d_in[1];   // (100000,256)
    const int*   pairs = (const int*)  d_in[2];   // (100000,2) int32
    const float* ctxw  = (const float*)d_in[3];   // (128,256)
    const float* ctxb  = (const float*)d_in[4];   // (128,)
    const float* bw    = (const float*)d_in[5];   // (256,384)
    const float* sw    = (const float*)d_in[6];   // (256,384,7)
    const float* ss    = (const float*)d_in[7];   // (256,384)
    const float* grid  = (const float*)d_in[8];   // (384,11)
    float* out = (float*)d_out;

    int nEdges = in_sizes[2] / 2;

    float *xc, *act, *weff;
    cudaGetSymbolAddress((void**)&xc,   g_xc);
    cudaGetSymbolAddress((void**)&act,  g_act);
    cudaGetSymbolAddress((void**)&weff, g_weff);

    // 0: fuse spline scaler into weights
    {
        int total = OUT_DIM * K_TOTAL;
        prep_weff<<<(total + 255) / 256, 256>>>(bw, sw, ss, weff);
    }

    // 1: ctx projection  xc = cemb @ ctxw^T + ctxb   (M=nEdges, N=128, K=256)
    {
        dim3 gridDim(1, (nEdges + 127) / 128);
        gemm_nt<<<gridDim, 256>>>(cemb, ctxw, ctxb, xc, nEdges, NODE_DIM, CTX_DIM);
    }

    // 2: activations
    {
        int total = nEdges * IN_DIM;
        build_act<<<(total + 255) / 256, 256>>>(node, xc, pairs, grid, act, nEdges);
    }

    // 3: main GEMM  out = act @ weff^T   (M=nEdges, N=256, K=3072)
    {
        dim3 gridDim(OUT_DIM / 128, (nEdges + 127) / 128);
        gemm_nt<<<gridDim, 256>>>(act, weff, nullptr, out, nEdges, OUT_DIM, K_TOTAL);
    }
}

// round 3
// speedup vs baseline: 1.6379x; 1.6379x over previous
#include <cuda_runtime.h>
#include <cuda_bf16.h>
#include <cstdint>

// ---------------- problem constants ----------------
#define NODE_DIM 128
#define CTX_DIM  256
#define OUT_DIM  256
#define IN_DIM   384
#define N_COEF   7
#define K_TOTAL  3072
#define MAX_EDGES 100000

typedef __nv_bfloat16 bf16;

// ---------------- device scratch (static) ----------------
__device__ float g_xc[(size_t)MAX_EDGES * NODE_DIM];
__device__ bf16  g_act_hi[(size_t)MAX_EDGES * K_TOTAL];
__device__ bf16  g_act_lo[(size_t)MAX_EDGES * K_TOTAL];
__device__ bf16  g_w_hi[(size_t)OUT_DIM * K_TOTAL];
__device__ bf16  g_w_lo[(size_t)OUT_DIM * K_TOTAL];
__device__ bf16  g_cemb_hi[(size_t)MAX_EDGES * CTX_DIM];
__device__ bf16  g_cemb_lo[(size_t)MAX_EDGES * CTX_DIM];
__device__ bf16  g_cw_hi[(size_t)NODE_DIM * CTX_DIM];
__device__ bf16  g_cw_lo[(size_t)NODE_DIM * CTX_DIM];

// ---------------- helpers ----------------
__device__ __forceinline__ uint32_t smem_u32(const void* p) {
    uint32_t a;
    asm("{ .reg .u64 t; cvta.to.shared.u64 t, %1; cvt.u32.u64 %0, t; }" : "=r"(a) : "l"(p));
    return a;
}
#define SWZ(x) ((x) ^ (((x) >> 3) & 0x70))

__device__ __forceinline__ void cp16(uint32_t saddr, const void* g, uint32_t sz) {
    asm volatile("cp.async.cg.shared.global [%0], [%1], 16, %2;\n"
                 :: "r"(saddr), "l"(g), "r"(sz));
}

__device__ __forceinline__ void ldm4(uint32_t* r, uint32_t addr) {
    asm volatile("ldmatrix.sync.aligned.m8n8.x4.shared.b16 {%0,%1,%2,%3}, [%4];"
                 : "=r"(r[0]), "=r"(r[1]), "=r"(r[2]), "=r"(r[3]) : "r"(addr));
}

__device__ __forceinline__ void mma16816(float* d, const uint32_t* a, const uint32_t* b) {
    asm volatile(
        "mma.sync.aligned.m16n8k16.row.col.f32.bf16.bf16.f32 "
        "{%0,%1,%2,%3}, {%4,%5,%6,%7}, {%8,%9}, {%0,%1,%2,%3};"
        : "+f"(d[0]), "+f"(d[1]), "+f"(d[2]), "+f"(d[3])
        : "r"(a[0]), "r"(a[1]), "r"(a[2]), "r"(a[3]), "r"(b[0]), "r"(b[1]));
}

// ---------------- weight prep ----------------
__global__ void prep_weff(const float* __restrict__ bw, const float* __restrict__ sw,
                          const float* __restrict__ ss, bf16* __restrict__ Wh,
                          bf16* __restrict__ Wl)
{
    int t = blockIdx.x * blockDim.x + threadIdx.x;
    if (t >= OUT_DIM * K_TOTAL) return;
    int o = t / K_TOTAL;
    int k = t - o * K_TOTAL;
    float v;
    if (k < IN_DIM) v = bw[o * IN_DIM + k];
    else {
        int r = k - IN_DIM;
        int i = r / N_COEF;
        int c = r - i * N_COEF;
        v = sw[((size_t)o * IN_DIM + i) * N_COEF + c] * ss[o * IN_DIM + i];
    }
    bf16 h = __float2bfloat16(v);
    Wh[t] = h;
    Wl[t] = __float2bfloat16(v - __bfloat162float(h));
}

__global__ void cvt_split(const float* __restrict__ src, bf16* __restrict__ hi,
                          bf16* __restrict__ lo, size_t n)
{
    size_t t = (size_t)blockIdx.x * blockDim.x + threadIdx.x;
    if (t >= n) return;
    float v = src[t];
    bf16 h = __float2bfloat16(v);
    hi[t] = h;
    lo[t] = __float2bfloat16(v - __bfloat162float(h));
}

// ---------------- mma.sync split-bf16 NT GEMM ----------------
// C[M,N] = (Ah+Al)(Bh+Bl)^T (+bias), fp32 accum/out. 3 passes: hh + hl + lh.
// BM=128, BN=128, BK=64, 256 thr, double-buffered cp.async, SW128 smem.
#define TILE_BYTES 16384                 // 128 rows x 128 bytes
#define OFF_AH 0
#define OFF_AL (TILE_BYTES)
#define OFF_BH (2 * TILE_BYTES)
#define OFF_BL (3 * TILE_BYTES)
#define STAGE_BYTES (4 * TILE_BYTES)     // 64 KB
#define SMEM_TOTAL (2 * STAGE_BYTES)     // 128 KB

__global__ void __launch_bounds__(256, 1)
mma_gemm(const bf16* __restrict__ Ah, const bf16* __restrict__ Al,
         const bf16* __restrict__ Bh, const bf16* __restrict__ Bl,
         const float* __restrict__ bias, float* __restrict__ C,
         int M, int N, int K)
{
    extern __shared__ char smem[];
    const uint32_t sbase = smem_u32(smem);
    const int tid = threadIdx.x;
    const int wid = tid >> 5;
    const int lid = tid & 31;
    const int m0 = blockIdx.y * 128;
    const int n0 = blockIdx.x * 128;

    const int warp_m = (wid >> 2) * 64;  // 2 warp-rows
    const int warp_n = (wid & 3) * 32;   // 4 warp-cols

    float acc[4][4][4];
#pragma unroll
    for (int i = 0; i < 4; ++i)
#pragma unroll
        for (int j = 0; j < 4; ++j)
#pragma unroll
            for (int q = 0; q < 4; ++q) acc[i][j][q] = 0.f;

    auto load_stage = [&](int t, int buf) {
        const uint32_t bb = sbase + buf * STAGE_BYTES;
        const int k0 = t * 64;
        // A: 128 rows x 8 chunks of 16B, hi+lo
        for (int i = tid; i < 1024; i += 256) {
            int row = i >> 3, c = i & 7;
            int m = m0 + row;
            uint32_t v = (m < M) ? 16u : 0u;
            size_t go = (size_t)(m < M ? m : 0) * K + k0 + c * 8;
            uint32_t so = SWZ(row * 128 + c * 16);
            cp16(bb + OFF_AH + so, Ah + go, v);
            cp16(bb + OFF_AL + so, Al + go, v);
        }
        // B: 128 rows x 8 chunks, hi+lo (N rows always valid: N in {128,256})
        for (int i = tid; i < 1024; i += 256) {
            int row = i >> 3, c = i & 7;
            size_t go = (size_t)(n0 + row) * K + k0 + c * 8;
            uint32_t so = SWZ(row * 128 + c * 16);
            cp16(bb + OFF_BH + so, Bh + go, 16u);
            cp16(bb + OFF_BL + so, Bl + go, 16u);
        }
        asm volatile("cp.async.commit_group;\n" ::: "memory");
    };

    const int nk = K / 64;
    load_stage(0, 0);

    for (int t = 0; t < nk; ++t) {
        const int buf = t & 1;
        if (t + 1 < nk) {
            load_stage(t + 1, buf ^ 1);
            asm volatile("cp.async.wait_group 1;\n" ::: "memory");
        } else {
            asm volatile("cp.async.wait_group 0;\n" ::: "memory");
        }
        __syncthreads();

        const uint32_t bb = sbase + buf * STAGE_BYTES;
#pragma unroll
        for (int ks = 0; ks < 4; ++ks) {
            uint32_t ah[4][4], al[4][4], bh[4][2], bl[4][2];
            // A fragments: lanes 0-7: m0-7@k0 | 8-15: m8-15@k0 | 16-23: m0-7@k8 | 24-31: m8-15@k8
            {
                uint32_t row_in = ((lid >> 3) & 1) * 8 + (lid & 7);
                uint32_t kb = ks * 32 + (lid >> 4) * 16;
#pragma unroll
                for (int mf = 0; mf < 4; ++mf) {
                    uint32_t off = SWZ((warp_m + mf * 16 + row_in) * 128 + kb);
                    ldm4(ah[mf], bb + OFF_AH + off);
                    ldm4(al[mf], bb + OFF_AL + off);
                }
            }
            // B fragments: lanes 0-7: n0-7@k0 | 8-15: n0-7@k8 | 16-23: n8-15@k0 | 24-31: n8-15@k8
            {
                uint32_t row_in = ((lid >> 4) & 1) * 8 + (lid & 7);
                uint32_t kb = ks * 32 + ((lid >> 3) & 1) * 16;
#pragma unroll
                for (int p = 0; p < 2; ++p) {
                    uint32_t off = SWZ((warp_n + p * 16 + row_in) * 128 + kb);
                    uint32_t r[4];
                    ldm4(r, bb + OFF_BH + off);
                    bh[2 * p][0] = r[0]; bh[2 * p][1] = r[1];
                    bh[2 * p + 1][0] = r[2]; bh[2 * p + 1][1] = r[3];
                    ldm4(r, bb + OFF_BL + off);
                    bl[2 * p][0] = r[0]; bl[2 * p][1] = r[1];
                    bl[2 * p + 1][0] = r[2]; bl[2 * p + 1][1] = r[3];
                }
            }
#pragma unroll
            for (int mf = 0; mf < 4; ++mf)
#pragma unroll
                for (int nf = 0; nf < 4; ++nf) {
                    mma16816(acc[mf][nf], ah[mf], bh[nf]);
                    mma16816(acc[mf][nf], ah[mf], bl[nf]);
                    mma16816(acc[mf][nf], al[mf], bh[nf]);
                }
        }
        __syncthreads();
    }

    // epilogue: d0,d1 -> row l>>2, cols (l&3)*2,+1 ; d2,d3 -> row +8
#pragma unroll
    for (int mf = 0; mf < 4; ++mf) {
        int r0 = m0 + warp_m + mf * 16 + (lid >> 2);
#pragma unroll
        for (int nf = 0; nf < 4; ++nf) {
            int col = n0 + warp_n + nf * 8 + (lid & 3) * 2;
            float b0 = 0.f, b1 = 0.f;
            if (bias) { b0 = bias[col]; b1 = bias[col + 1]; }
            if (r0 < M) {
                float2 v = make_float2(acc[mf][nf][0] + b0, acc[mf][nf][1] + b1);
                *reinterpret_cast<float2*>(&C[(size_t)r0 * N + col]) = v;
            }
            if (r0 + 8 < M) {
                float2 v = make_float2(acc[mf][nf][2] + b0, acc[mf][nf][3] + b1);
                *reinterpret_cast<float2*>(&C[(size_t)(r0 + 8) * N + col]) = v;
            }
        }
    }
}

// ---------------- activation builder ----------------
__global__ void build_act(const float* __restrict__ node, const float* __restrict__ xc,
                          const int* __restrict__ pairs, const float* __restrict__ grid,
                          bf16* __restrict__ acth, bf16* __restrict__ actl, int nEdges)
{
    __shared__ float g[11];
    __shared__ float inv[3][11];
    if (threadIdx.x < 11) g[threadIdx.x] = grid[threadIdx.x];  // grid rows identical
    __syncthreads();
    if (threadIdx.x < 11) {
        int j = threadIdx.x;
#pragma unroll
        for (int k = 1; k <= 3; ++k)
            if (j <= 10 - k) inv[k - 1][j] = 1.f / (g[j + k] - g[j]);
    }
    __syncthreads();

    int t = blockIdx.x * blockDim.x + threadIdx.x;
    if (t >= nEdges * IN_DIM) return;
    int n = t / IN_DIM;
    int i = t - n * IN_DIM;

    float x;
    if (i < NODE_DIM) {
        int p = pairs[2 * n];
        x = node[(size_t)p * NODE_DIM + i];
    } else if (i < 2 * NODE_DIM) {
        int p = pairs[2 * n + 1];
        x = node[(size_t)p * NODE_DIM + (i - NODE_DIM)];
    } else {
        x = xc[(size_t)n * NODE_DIM + (i - 2 * NODE_DIM)];
    }

    float s = x / (1.f + expf(-x));

    float b[10];
#pragma unroll
    for (int j = 0; j < 10; ++j) b[j] = (x >= g[j] && x < g[j + 1]) ? 1.f : 0.f;
#pragma unroll
    for (int k = 1; k <= 3; ++k) {
#pragma unroll
        for (int j = 0; j < 10; ++j) {
            if (j < 10 - k) {
                b[j] = (x - g[j]) * inv[k - 1][j] * b[j]
                     + (g[j + k + 1] - x) * inv[k - 1][j + 1] * b[j + 1];
            }
        }
    }

    size_t base = (size_t)n * K_TOTAL;
    {
        bf16 h = __float2bfloat16(s);
        acth[base + i] = h;
        actl[base + i] = __float2bfloat16(s - __bfloat162float(h));
    }
#pragma unroll
    for (int c = 0; c < N_COEF; ++c) {
        size_t idx = base + IN_DIM + (size_t)i * N_COEF + c;
        bf16 h = __float2bfloat16(b[c]);
        acth[idx] = h;
        actl[idx] = __float2bfloat16(b[c] - __bfloat162float(h));
    }
}

// ---------------------------------------------------------------------------
extern "C" void kernel_launch(void* const* d_in, const int* in_sizes, int n_in,
                              void* d_out, int out_size)
{
    const float* node  = (const float*)d_in[0];
    const float* cemb  = (const float*)d_in[1];
    const int*   pairs = (const int*)  d_in[2];
    const float* ctxw  = (const float*)d_in[3];
    const float* ctxb  = (const float*)d_in[4];
    const float* bw    = (const float*)d_in[5];
    const float* sw    = (const float*)d_in[6];
    const float* ss    = (const float*)d_in[7];
    const float* grid  = (const float*)d_in[8];
    float* out = (float*)d_out;

    int nEdges = in_sizes[2] / 2;

    float *xc;
    bf16 *acth, *actl, *wh, *wl, *ceh, *cel, *cwh, *cwl;
    cudaGetSymbolAddress((void**)&xc, g_xc);
    cudaGetSymbolAddress((void**)&acth, g_act_hi);
    cudaGetSymbolAddress((void**)&actl, g_act_lo);
    cudaGetSymbolAddress((void**)&wh, g_w_hi);
    cudaGetSymbolAddress((void**)&wl, g_w_lo);
    cudaGetSymbolAddress((void**)&ceh, g_cemb_hi);
    cudaGetSymbolAddress((void**)&cel, g_cemb_lo);
    cudaGetSymbolAddress((void**)&cwh, g_cw_hi);
    cudaGetSymbolAddress((void**)&cwl, g_cw_lo);

    cudaFuncSetAttribute(mma_gemm, cudaFuncAttributeMaxDynamicSharedMemorySize, SMEM_TOTAL);

    // 0: weight prep + input splits
    {
        int total = OUT_DIM * K_TOTAL;
        prep_weff<<<(total + 255) / 256, 256>>>(bw, sw, ss, wh, wl);
    }
    {
        size_t n = (size_t)NODE_DIM * CTX_DIM;
        cvt_split<<<(int)((n + 255) / 256), 256>>>(ctxw, cwh, cwl, n);
    }
    {
        size_t n = (size_t)nEdges * CTX_DIM;
        cvt_split<<<(int)((n + 255) / 256), 256>>>(cemb, ceh, cel, n);
    }

    // 1: ctx projection  xc = cemb @ ctxw^T + b  (M=nEdges, N=128, K=256)
    {
        dim3 grid(1, (nEdges + 127) / 128);
        mma_gemm<<<grid, 256, SMEM_TOTAL>>>(ceh, cel, cwh, cwl, ctxb, xc,
                                            nEdges, NODE_DIM, CTX_DIM);
    }

    // 2: activations (bf16 hi/lo)
    {
        int total = nEdges * IN_DIM;
        build_act<<<(total + 255) / 256, 256>>>(node, xc, pairs, grid, acth, actl, nEdges);
    }

    // 3: main GEMM  out = act @ weff^T  (M=nEdges, N=256, K=3072)
    {
        dim3 grid(OUT_DIM / 128, (nEdges + 127) / 128);
        mma_gemm<<<grid, 256, SMEM_TOTAL>>>(acth, actl, wh, wl, nullptr, out,
                                            nEdges, OUT_DIM, K_TOTAL);
    }
}

// round 4
// speedup vs baseline: 2.3382x; 1.4275x over previous
#include <cuda_runtime.h>
#include <cuda_bf16.h>
#include <cstdint>

// ---------------- problem constants ----------------
#define NODE_DIM 128
#define CTX_DIM  256
#define OUT_DIM  256
#define IN_DIM   384
#define N_COEF   7
#define K_TOTAL  3072
#define MAX_EDGES 100000

typedef __nv_bfloat16 bf16;

// ---------------- device scratch (static) ----------------
__device__ float g_xc[(size_t)MAX_EDGES * NODE_DIM];
__device__ bf16  g_act_hi[(size_t)MAX_EDGES * K_TOTAL];
__device__ bf16  g_act_lo[(size_t)MAX_EDGES * K_TOTAL];
__device__ bf16  g_w_hi[(size_t)OUT_DIM * K_TOTAL];
__device__ bf16  g_w_lo[(size_t)OUT_DIM * K_TOTAL];
__device__ bf16  g_cemb_hi[(size_t)MAX_EDGES * CTX_DIM];
__device__ bf16  g_cemb_lo[(size_t)MAX_EDGES * CTX_DIM];
__device__ bf16  g_cw_hi[(size_t)NODE_DIM * CTX_DIM];
__device__ bf16  g_cw_lo[(size_t)NODE_DIM * CTX_DIM];

// ---------------- helpers ----------------
__device__ __forceinline__ uint32_t smem_u32(const void* p) {
    uint32_t a;
    asm("{ .reg .u64 t; cvta.to.shared.u64 t, %1; cvt.u32.u64 %0, t; }" : "=r"(a) : "l"(p));
    return a;
}
#define SWZ(x) ((x) ^ (((x) >> 3) & 0x70))

__device__ __forceinline__ void cp16(uint32_t saddr, const void* g, uint32_t sz) {
    asm volatile("cp.async.cg.shared.global [%0], [%1], 16, %2;\n"
                 :: "r"(saddr), "l"(g), "r"(sz));
}

__device__ __forceinline__ void ldm4(uint32_t* r, uint32_t addr) {
    asm volatile("ldmatrix.sync.aligned.m8n8.x4.shared.b16 {%0,%1,%2,%3}, [%4];"
                 : "=r"(r[0]), "=r"(r[1]), "=r"(r[2]), "=r"(r[3]) : "r"(addr));
}

__device__ __forceinline__ void mma16816(float* d, const uint32_t* a, const uint32_t* b) {
    asm volatile(
        "mma.sync.aligned.m16n8k16.row.col.f32.bf16.bf16.f32 "
        "{%0,%1,%2,%3}, {%4,%5,%6,%7}, {%8,%9}, {%0,%1,%2,%3};"
        : "+f"(d[0]), "+f"(d[1]), "+f"(d[2]), "+f"(d[3])
        : "r"(a[0]), "r"(a[1]), "r"(a[2]), "r"(a[3]), "r"(b[0]), "r"(b[1]));
}

// ---------------- weight prep (coefficient-major spline layout) ------------
// K layout: k<384 -> base weights; k>=384 -> c = (k-384)/384, i = (k-384)%384
__global__ void prep_weff(const float* __restrict__ bw, const float* __restrict__ sw,
                          const float* __restrict__ ss, bf16* __restrict__ Wh,
                          bf16* __restrict__ Wl)
{
    int t = blockIdx.x * blockDim.x + threadIdx.x;
    if (t >= OUT_DIM * K_TOTAL) return;
    int o = t / K_TOTAL;
    int k = t - o * K_TOTAL;
    float v;
    if (k < IN_DIM) v = bw[o * IN_DIM + k];
    else {
        int r = k - IN_DIM;
        int c = r / IN_DIM;
        int i = r - c * IN_DIM;
        v = sw[((size_t)o * IN_DIM + i) * N_COEF + c] * ss[o * IN_DIM + i];
    }
    bf16 h = __float2bfloat16(v);
    Wh[t] = h;
    Wl[t] = __float2bfloat16(v - __bfloat162float(h));
}

__global__ void cvt_split(const float* __restrict__ src, bf16* __restrict__ hi,
                          bf16* __restrict__ lo, size_t n)
{
    size_t t = (size_t)blockIdx.x * blockDim.x + threadIdx.x;
    if (t >= n) return;
    float v = src[t];
    bf16 h = __float2bfloat16(v);
    hi[t] = h;
    lo[t] = __float2bfloat16(v - __bfloat162float(h));
}

// ---------------- mma.sync split-bf16 NT GEMM ----------------
// C = (Ah+Al)(Bh+Bl)^T (+bias); 3 passes hh+hl+lh, pass-major to break RAW.
// BM=128, BN=128, BK=64, 256 thr, 3-stage cp.async pipeline, SW128 smem.
#define TILE_BYTES 16384                 // 128 rows x 128 bytes
#define OFF_AH 0
#define OFF_AL (TILE_BYTES)
#define OFF_BH (2 * TILE_BYTES)
#define OFF_BL (3 * TILE_BYTES)
#define STAGE_BYTES (4 * TILE_BYTES)     // 64 KB
#define NSTAGE 3
#define SMEM_TOTAL (NSTAGE * STAGE_BYTES) // 192 KB

__global__ void __launch_bounds__(256, 1)
mma_gemm(const bf16* __restrict__ Ah, const bf16* __restrict__ Al,
         const bf16* __restrict__ Bh, const bf16* __restrict__ Bl,
         const float* __restrict__ bias, float* __restrict__ C,
         int M, int N, int K)
{
    extern __shared__ char smem[];
    const uint32_t sbase = smem_u32(smem);
    const int tid = threadIdx.x;
    const int wid = tid >> 5;
    const int lid = tid & 31;
    const int m0 = blockIdx.y * 128;
    const int n0 = blockIdx.x * 128;

    const int warp_m = (wid >> 2) * 64;
    const int warp_n = (wid & 3) * 32;

    float acc[4][4][4];
#pragma unroll
    for (int i = 0; i < 4; ++i)
#pragma unroll
        for (int j = 0; j < 4; ++j)
#pragma unroll
            for (int q = 0; q < 4; ++q) acc[i][j][q] = 0.f;

    auto load_stage = [&](int t, int buf) {
        const uint32_t bb = sbase + buf * STAGE_BYTES;
        const int k0 = t * 64;
        for (int i = tid; i < 1024; i += 256) {
            int row = i >> 3, c = i & 7;
            int m = m0 + row;
            uint32_t v = (m < M) ? 16u : 0u;   // size-0 cp.async zero-fills
            size_t go = (size_t)(m < M ? m : 0) * K + k0 + c * 8;
            uint32_t so = SWZ(row * 128 + c * 16);
            cp16(bb + OFF_AH + so, Ah + go, v);
            cp16(bb + OFF_AL + so, Al + go, v);
        }
        for (int i = tid; i < 1024; i += 256) {
            int row = i >> 3, c = i & 7;
            size_t go = (size_t)(n0 + row) * K + k0 + c * 8;
            uint32_t so = SWZ(row * 128 + c * 16);
            cp16(bb + OFF_BH + so, Bh + go, 16u);
            cp16(bb + OFF_BL + so, Bl + go, 16u);
        }
        asm volatile("cp.async.commit_group;\n" ::: "memory");
    };

    const int nk = K / 64;
    load_stage(0, 0);
    if (nk > 1) load_stage(1, 1);

    for (int t = 0; t < nk; ++t) {
        __syncthreads();   // protect buffer (t+2)%3 (consumed at iter t-1)
        if (t + 2 < nk) load_stage(t + 2, (t + 2) % NSTAGE);

        int rem = nk - t - 1;
        if (rem >= 2)      asm volatile("cp.async.wait_group 2;\n" ::: "memory");
        else if (rem == 1) asm volatile("cp.async.wait_group 1;\n" ::: "memory");
        else               asm volatile("cp.async.wait_group 0;\n" ::: "memory");
        __syncthreads();

        const uint32_t bb = sbase + (t % NSTAGE) * STAGE_BYTES;
#pragma unroll
        for (int ks = 0; ks < 4; ++ks) {
            uint32_t ah[4][4], al[4][4], bh[4][2], bl[4][2];
            {
                uint32_t row_in = ((lid >> 3) & 1) * 8 + (lid & 7);
                uint32_t kb = ks * 32 + (lid >> 4) * 16;
#pragma unroll
                for (int mf = 0; mf < 4; ++mf) {
                    uint32_t off = SWZ((warp_m + mf * 16 + row_in) * 128 + kb);
                    ldm4(ah[mf], bb + OFF_AH + off);
                    ldm4(al[mf], bb + OFF_AL + off);
                }
            }
            {
                uint32_t row_in = ((lid >> 4) & 1) * 8 + (lid & 7);
                uint32_t kb = ks * 32 + ((lid >> 3) & 1) * 16;
#pragma unroll
                for (int p = 0; p < 2; ++p) {
                    uint32_t off = SWZ((warp_n + p * 16 + row_in) * 128 + kb);
                    uint32_t r[4];
                    ldm4(r, bb + OFF_BH + off);
                    bh[2 * p][0] = r[0]; bh[2 * p][1] = r[1];
                    bh[2 * p + 1][0] = r[2]; bh[2 * p + 1][1] = r[3];
                    ldm4(r, bb + OFF_BL + off);
                    bl[2 * p][0] = r[0]; bl[2 * p][1] = r[1];
                    bl[2 * p + 1][0] = r[2]; bl[2 * p + 1][1] = r[3];
                }
            }
            // pass-major: 16 independent MMAs between accumulator reuses
#pragma unroll
            for (int mf = 0; mf < 4; ++mf)
#pragma unroll
                for (int nf = 0; nf < 4; ++nf)
                    mma16816(acc[mf][nf], ah[mf], bh[nf]);
#pragma unroll
            for (int mf = 0; mf < 4; ++mf)
#pragma unroll
                for (int nf = 0; nf < 4; ++nf)
                    mma16816(acc[mf][nf], ah[mf], bl[nf]);
#pragma unroll
            for (int mf = 0; mf < 4; ++mf)
#pragma unroll
                for (int nf = 0; nf < 4; ++nf)
                    mma16816(acc[mf][nf], al[mf], bh[nf]);
        }
    }

    // epilogue
#pragma unroll
    for (int mf = 0; mf < 4; ++mf) {
        int r0 = m0 + warp_m + mf * 16 + (lid >> 2);
#pragma unroll
        for (int nf = 0; nf < 4; ++nf) {
            int col = n0 + warp_n + nf * 8 + (lid & 3) * 2;
            float b0 = 0.f, b1 = 0.f;
            if (bias) { b0 = bias[col]; b1 = bias[col + 1]; }
            if (r0 < M) {
                float2 v = make_float2(acc[mf][nf][0] + b0, acc[mf][nf][1] + b1);
                *reinterpret_cast<float2*>(&C[(size_t)r0 * N + col]) = v;
            }
            if (r0 + 8 < M) {
                float2 v = make_float2(acc[mf][nf][2] + b0, acc[mf][nf][3] + b1);
                *reinterpret_cast<float2*>(&C[(size_t)(r0 + 8) * N + col]) = v;
            }
        }
    }
}

// ---------------- activation builder (coefficient-major spline layout) -----
__global__ void build_act(const float* __restrict__ node, const float* __restrict__ xc,
                          const int* __restrict__ pairs, const float* __restrict__ grid,
                          bf16* __restrict__ acth, bf16* __restrict__ actl, int nEdges)
{
    __shared__ float g[11];
    __shared__ float inv[3][11];
    if (threadIdx.x < 11) g[threadIdx.x] = grid[threadIdx.x];  // grid rows identical
    __syncthreads();
    if (threadIdx.x < 11) {
        int j = threadIdx.x;
#pragma unroll
        for (int k = 1; k <= 3; ++k)
            if (j <= 10 - k) inv[k - 1][j] = 1.f / (g[j + k] - g[j]);
    }
    __syncthreads();

    int t = blockIdx.x * blockDim.x + threadIdx.x;
    if (t >= nEdges * IN_DIM) return;
    int n = t / IN_DIM;
    int i = t - n * IN_DIM;

    float x;
    if (i < NODE_DIM) {
        int p = pairs[2 * n];
        x = node[(size_t)p * NODE_DIM + i];
    } else if (i < 2 * NODE_DIM) {
        int p = pairs[2 * n + 1];
        x = node[(size_t)p * NODE_DIM + (i - NODE_DIM)];
    } else {
        x = xc[(size_t)n * NODE_DIM + (i - 2 * NODE_DIM)];
    }

    float s = x / (1.f + expf(-x));

    float b[10];
#pragma unroll
    for (int j = 0; j < 10; ++j) b[j] = (x >= g[j] && x < g[j + 1]) ? 1.f : 0.f;
#pragma unroll
    for (int k = 1; k <= 3; ++k) {
#pragma unroll
        for (int j = 0; j < 10; ++j) {
            if (j < 10 - k) {
                b[j] = (x - g[j]) * inv[k - 1][j] * b[j]
                     + (g[j + k + 1] - x) * inv[k - 1][j + 1] * b[j + 1];
            }
        }
    }

    size_t base = (size_t)n * K_TOTAL;
    {
        bf16 h = __float2bfloat16(s);
        acth[base + i] = h;
        actl[base + i] = __float2bfloat16(s - __bfloat162float(h));
    }
#pragma unroll
    for (int c = 0; c < N_COEF; ++c) {
        size_t idx = base + IN_DIM + (size_t)c * IN_DIM + i;   // coalesced over i
        bf16 h = __float2bfloat16(b[c]);
        acth[idx] = h;
        actl[idx] = __float2bfloat16(b[c] - __bfloat162float(h));
    }
}

// ---------------------------------------------------------------------------
extern "C" void kernel_launch(void* const* d_in, const int* in_sizes, int n_in,
                              void* d_out, int out_size)
{
    const float* node  = (const float*)d_in[0];
    const float* cemb  = (const float*)d_in[1];
    const int*   pairs = (const int*)  d_in[2];
    const float* ctxw  = (const float*)d_in[3];
    const float* ctxb  = (const float*)d_in[4];
    const float* bw    = (const float*)d_in[5];
    const float* sw    = (const float*)d_in[6];
    const float* ss    = (const float*)d_in[7];
    const float* grid  = (const float*)d_in[8];
    float* out = (float*)d_out;

    int nEdges = in_sizes[2] / 2;

    float *xc;
    bf16 *acth, *actl, *wh, *wl, *ceh, *cel, *cwh, *cwl;
    cudaGetSymbolAddress((void**)&xc, g_xc);
    cudaGetSymbolAddress((void**)&acth, g_act_hi);
    cudaGetSymbolAddress((void**)&actl, g_act_lo);
    cudaGetSymbolAddress((void**)&wh, g_w_hi);
    cudaGetSymbolAddress((void**)&wl, g_w_lo);
    cudaGetSymbolAddress((void**)&ceh, g_cemb_hi);
    cudaGetSymbolAddress((void**)&cel, g_cemb_lo);
    cudaGetSymbolAddress((void**)&cwh, g_cw_hi);
    cudaGetSymbolAddress((void**)&cwl, g_cw_lo);

    cudaFuncSetAttribute(mma_gemm, cudaFuncAttributeMaxDynamicSharedMemorySize, SMEM_TOTAL);

    {
        int total = OUT_DIM * K_TOTAL;
        prep_weff<<<(total + 255) / 256, 256>>>(bw, sw, ss, wh, wl);
    }
    {
        size_t n = (size_t)NODE_DIM * CTX_DIM;
        cvt_split<<<(int)((n + 255) / 256), 256>>>(ctxw, cwh, cwl, n);
    }
    {
        size_t n = (size_t)nEdges * CTX_DIM;
        cvt_split<<<(int)((n + 255) / 256), 256>>>(cemb, ceh, cel, n);
    }

    // ctx projection  xc = cemb @ ctxw^T + b  (M=nEdges, N=128, K=256)
    {
        dim3 grid(1, (nEdges + 127) / 128);
        mma_gemm<<<grid, 256, SMEM_TOTAL>>>(ceh, cel, cwh, cwl, ctxb, xc,
                                            nEdges, NODE_DIM, CTX_DIM);
    }

    // activations
    {
        int total = nEdges * IN_DIM;
        build_act<<<(total + 255) / 256, 256>>>(node, xc, pairs, grid, acth, actl, nEdges);
    }

    // main GEMM  out = act @ weff^T  (M=nEdges, N=256, K=3072)
    {
        dim3 grid(OUT_DIM / 128, (nEdges + 127) / 128);
        mma_gemm<<<grid, 256, SMEM_TOTAL>>>(acth, actl, wh, wl, nullptr, out,
                                            nEdges, OUT_DIM, K_TOTAL);
    }
}